// round 1
// baseline (speedup 1.0000x reference)
#include <cuda_runtime.h>

#define BB   4
#define HH   256
#define WW   256
#define CC   64      // feature channels
#define CIN  3
#define OFFC 18      // 2*K*K

// Scratch (allocation-free): feat in NHWC, offsets in NHWC
__device__ float g_feat[BB * HH * WW * CC];    // [b][h][w][c]  (~67 MB)
__device__ float g_off [BB * HH * WW * OFFC];  // [b][h][w][oc] (~19 MB)

// ---------------------------------------------------------------------------
// Kernel 1: x [B,3,H,W] (NCHW) -> feat [B,H,W,64] (NHWC), 3x3 conv, pad 1
// ---------------------------------------------------------------------------
__global__ void conv_in_kernel(const float* __restrict__ x,
                               const float* __restrict__ cw,
                               const float* __restrict__ cb) {
    __shared__ float sw[CIN * 9 * CC];   // [ci][tap][o]
    __shared__ float sb[CC];
    const int b = blockIdx.x / HH;
    const int h = blockIdx.x % HH;
    const int w = threadIdx.x;

    for (int idx = threadIdx.x; idx < CIN * 9 * CC; idx += blockDim.x) {
        int o = idx % CC;
        int rest = idx / CC;               // ci*9 + tap
        sw[idx] = cw[o * (CIN * 9) + rest];
    }
    if (threadIdx.x < CC) sb[threadIdx.x] = cb[threadIdx.x];
    __syncthreads();

    float acc[CC];
    #pragma unroll
    for (int o = 0; o < CC; o++) acc[o] = sb[o];

    #pragma unroll
    for (int ci = 0; ci < CIN; ci++) {
        #pragma unroll
        for (int i = 0; i < 3; i++) {
            int y = h - 1 + i;
            #pragma unroll
            for (int j = 0; j < 3; j++) {
                int xx = w - 1 + j;
                float v = 0.0f;
                if (y >= 0 && y < HH && xx >= 0 && xx < WW)
                    v = x[((b * CIN + ci) * HH + y) * WW + xx];
                const float* wp = &sw[(ci * 9 + i * 3 + j) * CC];
                #pragma unroll
                for (int o = 0; o < CC; o++)
                    acc[o] = fmaf(v, wp[o], acc[o]);
            }
        }
    }

    float* fp = &g_feat[(((b * HH + h) * WW) + w) * CC];
    #pragma unroll
    for (int o = 0; o < CC; o += 4) {
        float4 t = make_float4(acc[o], acc[o + 1], acc[o + 2], acc[o + 3]);
        *reinterpret_cast<float4*>(fp + o) = t;
    }
}

// ---------------------------------------------------------------------------
// Kernel 2: feat NHWC -> offset [B,H,W,18] NHWC, 3x3 conv, pad 1
// ---------------------------------------------------------------------------
__global__ void conv_off_kernel(const float* __restrict__ ow,
                                const float* __restrict__ ob) {
    __shared__ float sw[CC * 9 * OFFC];   // [c][tap][oc] = 10368 floats (41.5 KB)
    __shared__ float sb[OFFC];
    const int b = blockIdx.x / HH;
    const int h = blockIdx.x % HH;
    const int w = threadIdx.x;

    for (int idx = threadIdx.x; idx < CC * 9 * OFFC; idx += blockDim.x) {
        int oc = idx % OFFC;
        int rest = idx / OFFC;             // c*9 + tap
        sw[idx] = ow[oc * (CC * 9) + rest];
    }
    if (threadIdx.x < OFFC) sb[threadIdx.x] = ob[threadIdx.x];
    __syncthreads();

    float acc[OFFC];
    #pragma unroll
    for (int o = 0; o < OFFC; o++) acc[o] = sb[o];

    #pragma unroll
    for (int i = 0; i < 3; i++) {
        int y = h - 1 + i;
        bool yv = (y >= 0 && y < HH);
        #pragma unroll
        for (int j = 0; j < 3; j++) {
            int xx = w - 1 + j;
            bool v = yv && (xx >= 0 && xx < WW);
            int yc = v ? y : 0;
            int xc = v ? xx : 0;
            const float4* fp = reinterpret_cast<const float4*>(
                &g_feat[(((b * HH + yc) * WW) + xc) * CC]);
            const int tap = i * 3 + j;
            for (int c4 = 0; c4 < CC / 4; c4++) {
                float4 f = v ? fp[c4] : make_float4(0.f, 0.f, 0.f, 0.f);
                const float* fv = reinterpret_cast<const float*>(&f);
                #pragma unroll
                for (int cc = 0; cc < 4; cc++) {
                    float s = fv[cc];
                    const float* wp = &sw[((c4 * 4 + cc) * 9 + tap) * OFFC];
                    #pragma unroll
                    for (int o = 0; o < OFFC; o++)
                        acc[o] = fmaf(s, wp[o], acc[o]);
                }
            }
        }
    }

    float* op = &g_off[(((b * HH + h) * WW) + w) * OFFC];
    #pragma unroll
    for (int o = 0; o < OFFC; o++) op[o] = acc[o];
}

// ---------------------------------------------------------------------------
// Kernel 3: deformable conv. feat NHWC + offset NHWC -> out [B,64,H,W] NCHW
// ---------------------------------------------------------------------------
__global__ void deform_kernel(const float* __restrict__ dw,
                              const float* __restrict__ db,
                              float* __restrict__ out) {
    __shared__ float sw[CC * CC];   // per-tap weight tile [c][o], 16 KB
    const int b = blockIdx.x / HH;
    const int h = blockIdx.x % HH;
    const int w = threadIdx.x;
    const int pix = ((b * HH + h) * WW) + w;
    const float* offp = &g_off[pix * OFFC];

    float acc[CC];
    #pragma unroll
    for (int o = 0; o < CC; o++) acc[o] = 0.0f;

    for (int k = 0; k < 9; k++) {
        __syncthreads();
        for (int idx = threadIdx.x; idx < CC * CC; idx += blockDim.x) {
            int o = idx % CC;
            int c = idx / CC;
            sw[idx] = dw[(o * CC + c) * 9 + k];
        }
        __syncthreads();

        const int i = k / 3, j = k % 3;
        float sy = (float)(h - 1 + i) + offp[2 * k];
        float sx = (float)(w - 1 + j) + offp[2 * k + 1];
        float y0f = floorf(sy), x0f = floorf(sx);
        float dy = sy - y0f, dx = sx - x0f;
        int y0 = (int)y0f, x0 = (int)x0f;
        int y1 = y0 + 1,   x1 = x0 + 1;

        bool vy0 = (y0 >= 0 && y0 < HH), vy1 = (y1 >= 0 && y1 < HH);
        bool vx0 = (x0 >= 0 && x0 < WW), vx1 = (x1 >= 0 && x1 < WW);

        float w00 = (1.f - dy) * (1.f - dx) * ((vy0 && vx0) ? 1.f : 0.f);
        float w01 = (1.f - dy) * dx         * ((vy0 && vx1) ? 1.f : 0.f);
        float w10 = dy * (1.f - dx)         * ((vy1 && vx0) ? 1.f : 0.f);
        float w11 = dy * dx                 * ((vy1 && vx1) ? 1.f : 0.f);

        int y0c = min(max(y0, 0), HH - 1), y1c = min(max(y1, 0), HH - 1);
        int x0c = min(max(x0, 0), WW - 1), x1c = min(max(x1, 0), WW - 1);

        const float4* p00 = reinterpret_cast<const float4*>(
            &g_feat[(((b * HH + y0c) * WW) + x0c) * CC]);
        const float4* p01 = reinterpret_cast<const float4*>(
            &g_feat[(((b * HH + y0c) * WW) + x1c) * CC]);
        const float4* p10 = reinterpret_cast<const float4*>(
            &g_feat[(((b * HH + y1c) * WW) + x0c) * CC]);
        const float4* p11 = reinterpret_cast<const float4*>(
            &g_feat[(((b * HH + y1c) * WW) + x1c) * CC]);

        #pragma unroll 2
        for (int c4 = 0; c4 < CC / 4; c4++) {
            float4 f00 = p00[c4], f01 = p01[c4], f10 = p10[c4], f11 = p11[c4];
            float sv0 = w00 * f00.x + w01 * f01.x + w10 * f10.x + w11 * f11.x;
            float sv1 = w00 * f00.y + w01 * f01.y + w10 * f10.y + w11 * f11.y;
            float sv2 = w00 * f00.z + w01 * f01.z + w10 * f10.z + w11 * f11.z;
            float sv3 = w00 * f00.w + w01 * f01.w + w10 * f10.w + w11 * f11.w;

            const float* wp = &sw[(c4 * 4) * CC];
            #pragma unroll
            for (int o = 0; o < CC; o++) acc[o] = fmaf(sv0, wp[o], acc[o]);
            wp += CC;
            #pragma unroll
            for (int o = 0; o < CC; o++) acc[o] = fmaf(sv1, wp[o], acc[o]);
            wp += CC;
            #pragma unroll
            for (int o = 0; o < CC; o++) acc[o] = fmaf(sv2, wp[o], acc[o]);
            wp += CC;
            #pragma unroll
            for (int o = 0; o < CC; o++) acc[o] = fmaf(sv3, wp[o], acc[o]);
        }
    }

    #pragma unroll
    for (int o = 0; o < CC; o++)
        out[((b * CC + o) * HH + h) * WW + w] = acc[o] + db[o];
}

// ---------------------------------------------------------------------------
extern "C" void kernel_launch(void* const* d_in, const int* in_sizes, int n_in,
                              void* d_out, int out_size) {
    const float* x        = (const float*)d_in[0];
    const float* conv_w   = (const float*)d_in[1];
    const float* conv_b   = (const float*)d_in[2];
    const float* offset_w = (const float*)d_in[3];
    const float* offset_b = (const float*)d_in[4];
    const float* deform_w = (const float*)d_in[5];
    const float* deform_b = (const float*)d_in[6];
    float* out = (float*)d_out;

    dim3 grid(BB * HH);
    dim3 block(WW);

    conv_in_kernel<<<grid, block>>>(x, conv_w, conv_b);
    conv_off_kernel<<<grid, block>>>(offset_w, offset_b);
    deform_kernel<<<grid, block>>>(deform_w, deform_b, out);
}

// round 2
// speedup vs baseline: 1.5846x; 1.5846x over previous
#include <cuda_runtime.h>

#define BB   4
#define HH   256
#define WW   256
#define CC   64
#define CIN  3
#define OFFC 18
#define OFFP 20      // padded stride for 16B-aligned weight rows
#define NP   16      // channel planes (c/4)

// Scratch (allocation-free)
__device__ float4 g_feat[NP * BB * HH * WW];       // NC4HW4 feature layout, 67MB
__device__ float  g_off [BB * HH * WW * OFFC];     // NHWC offsets
__device__ float  g_cwT [CIN * 9 * CC];            // transposed weights
__device__ float  g_owT [CC * 9 * OFFP];
__device__ float  g_dwT [9 * CC * CC];             // [k][c][o]

typedef unsigned long long ull;

__device__ __forceinline__ ull pack2(float lo, float hi) {
    ull r; asm("mov.b64 %0, {%1,%2};" : "=l"(r) : "f"(lo), "f"(hi)); return r;
}
__device__ __forceinline__ float2 unpack2(ull v) {
    float2 r; asm("mov.b64 {%0,%1}, %2;" : "=f"(r.x), "=f"(r.y) : "l"(v)); return r;
}
#define FMA2(a, x, y) asm("fma.rn.f32x2 %0, %1, %2, %0;" : "+l"(a) : "l"(x), "l"(y))

// ---------------------------------------------------------------------------
// Prep: transpose weights so per-block smem fills are coalesced
// ---------------------------------------------------------------------------
__global__ void prep_kernel(const float* __restrict__ cw,
                            const float* __restrict__ ow,
                            const float* __restrict__ dw) {
    int t = blockIdx.x * blockDim.x + threadIdx.x;
    int nt = gridDim.x * blockDim.x;
    for (int idx = t; idx < CIN * 9 * CC; idx += nt) {
        int o = idx % CC, r = idx / CC;              // r = ci*9+tap
        g_cwT[idx] = cw[o * (CIN * 9) + r];
    }
    for (int idx = t; idx < CC * 9 * OFFP; idx += nt) {
        int oc = idx % OFFP, ct = idx / OFFP;        // ct = c*9+tap
        g_owT[idx] = (oc < OFFC) ? ow[oc * (CC * 9) + ct] : 0.0f;
    }
    for (int idx = t; idx < 9 * CC * CC; idx += nt) {
        int o = idx % CC, c = (idx / CC) % CC, k = idx / (CC * CC);
        g_dwT[idx] = dw[(o * CC + c) * 9 + k];
    }
}

// ---------------------------------------------------------------------------
// Kernel 1: x NCHW -> feat NC4HW4, 3x3 conv pad 1
// ---------------------------------------------------------------------------
__global__ void __launch_bounds__(256) conv_in_kernel(const float* __restrict__ x,
                                                      const float* __restrict__ cb) {
    __shared__ __align__(16) float sw[CIN * 9 * CC];
    __shared__ float sb[CC];
    for (int idx = threadIdx.x; idx < CIN * 9 * CC; idx += 256) sw[idx] = g_cwT[idx];
    if (threadIdx.x < CC) sb[threadIdx.x] = cb[threadIdx.x];
    __syncthreads();

    const int b = blockIdx.x / HH, h = blockIdx.x % HH, w = threadIdx.x;

    ull acc[32];
    #pragma unroll
    for (int q = 0; q < 32; q++) acc[q] = pack2(sb[2 * q], sb[2 * q + 1]);

    #pragma unroll 1
    for (int ci = 0; ci < CIN; ci++) {
        #pragma unroll
        for (int i = 0; i < 3; i++) {
            int y = h - 1 + i;
            bool yv = ((unsigned)y < HH);
            #pragma unroll
            for (int j = 0; j < 3; j++) {
                int xx = w - 1 + j;
                float v = (yv && (unsigned)xx < WW) ? x[((b * CIN + ci) * HH + y) * WW + xx] : 0.0f;
                ull s2 = pack2(v, v);
                const ulonglong2* wp = (const ulonglong2*)&sw[(ci * 9 + i * 3 + j) * CC];
                #pragma unroll
                for (int q = 0; q < 16; q++) {
                    ulonglong2 ww = wp[q];
                    FMA2(acc[2 * q], s2, ww.x);
                    FMA2(acc[2 * q + 1], s2, ww.y);
                }
            }
        }
    }

    const int ppix = h * WW + w;
    #pragma unroll
    for (int q4 = 0; q4 < NP; q4++) {
        float2 lo = unpack2(acc[2 * q4]);
        float2 hi = unpack2(acc[2 * q4 + 1]);
        g_feat[(q4 * BB + b) * HH * WW + ppix] = make_float4(lo.x, lo.y, hi.x, hi.y);
    }
}

// ---------------------------------------------------------------------------
// Kernel 2: feat NC4HW4 -> offsets NHWC(18). 2 rows per block.
// ---------------------------------------------------------------------------
__global__ void __launch_bounds__(256) conv_off_kernel(const float* __restrict__ ob) {
    __shared__ __align__(16) float sw[CC * 9 * OFFP];   // 46080 B
    for (int idx = threadIdx.x; idx < CC * 9 * OFFP; idx += 256) sw[idx] = g_owT[idx];
    __syncthreads();

    const int b = blockIdx.x / (HH / 2);
    const int h0 = (blockIdx.x % (HH / 2)) * 2;
    const int w = threadIdx.x;

    ull accA[9], accB[9];
    #pragma unroll
    for (int q = 0; q < 9; q++) {
        ull t = pack2(ob[2 * q], ob[2 * q + 1]);
        accA[q] = t; accB[q] = t;
    }

    #pragma unroll 1
    for (int i = 0; i < 3; i++) {
        int yA = h0 - 1 + i, yB = h0 + i;
        bool yAv = ((unsigned)yA < HH), yBv = ((unsigned)yB < HH);
        #pragma unroll 1
        for (int j = 0; j < 3; j++) {
            int xx = w - 1 + j;
            bool xv = ((unsigned)xx < WW);
            bool vA = yAv && xv, vB = yBv && xv;
            int xc = xv ? xx : 0;
            int iA = (vA ? yA : 0) * WW + xc;
            int iB = (vB ? yB : 0) * WW + xc;
            const int tap = i * 3 + j;
            #pragma unroll 1
            for (int c4 = 0; c4 < NP; c4++) {
                const float4* pc = g_feat + (c4 * BB + b) * HH * WW;
                float4 fa = vA ? pc[iA] : make_float4(0.f, 0.f, 0.f, 0.f);
                float4 fb = vB ? pc[iB] : make_float4(0.f, 0.f, 0.f, 0.f);
                const float fav[4] = {fa.x, fa.y, fa.z, fa.w};
                const float fbv[4] = {fb.x, fb.y, fb.z, fb.w};
                #pragma unroll
                for (int cc = 0; cc < 4; cc++) {
                    ull sa = pack2(fav[cc], fav[cc]);
                    ull sb2 = pack2(fbv[cc], fbv[cc]);
                    const float* wrow = &sw[((c4 * 4 + cc) * 9 + tap) * OFFP];
                    const ulonglong2* wp = (const ulonglong2*)wrow;
                    #pragma unroll
                    for (int q2 = 0; q2 < 4; q2++) {
                        ulonglong2 ww = wp[q2];
                        FMA2(accA[2 * q2], sa, ww.x);
                        FMA2(accA[2 * q2 + 1], sa, ww.y);
                        FMA2(accB[2 * q2], sb2, ww.x);
                        FMA2(accB[2 * q2 + 1], sb2, ww.y);
                    }
                    ull w8 = *(const ull*)(wrow + 16);
                    FMA2(accA[8], sa, w8);
                    FMA2(accB[8], sb2, w8);
                }
            }
        }
    }

    float* opA = &g_off[((b * HH + h0) * WW + w) * OFFC];
    float* opB = opA + WW * OFFC;
    #pragma unroll
    for (int q = 0; q < 9; q++) {
        ((float2*)opA)[q] = unpack2(accA[q]);
        ((float2*)opB)[q] = unpack2(accB[q]);
    }
}

// ---------------------------------------------------------------------------
// Kernel 3: deformable conv. 512 threads: 256 pixels (2 rows) x 2 o-halves.
// All 9 tap weight tiles resident in 144KB dynamic shared.
// ---------------------------------------------------------------------------
__global__ void __launch_bounds__(512, 1) deform_kernel(const float* __restrict__ db,
                                                        float* __restrict__ out) {
    extern __shared__ __align__(16) float sw[];   // 9*64*64 floats
    const int tid = threadIdx.x;
    {
        const float4* s4 = (const float4*)g_dwT;
        float4* d4 = (float4*)sw;
        for (int idx = tid; idx < 9 * CC * CC / 4; idx += 512) d4[idx] = s4[idx];
    }
    __syncthreads();

    const int w = tid & (WW - 1);
    const int half = tid >> 8;
    const int oBase = half * 32;
    const int b = blockIdx.x / (HH / 2);
    const int h0 = (blockIdx.x % (HH / 2)) * 2;

    const float* offA = &g_off[((b * HH + h0) * WW + w) * OFFC];
    const float* offB = offA + WW * OFFC;

    ull accA[16], accB[16];
    #pragma unroll
    for (int q = 0; q < 16; q++) { accA[q] = 0ull; accB[q] = 0ull; }

    #pragma unroll 1
    for (int k = 0; k < 9; k++) {
        const int i = k / 3, j = k % 3;

        float wA00, wA01, wA10, wA11; int iA00, iA01, iA10, iA11;
        {
            float sy = (float)(h0 - 1 + i) + offA[2 * k];
            float sx = (float)(w - 1 + j) + offA[2 * k + 1];
            float y0f = floorf(sy), x0f = floorf(sx);
            float dy = sy - y0f, dx = sx - x0f;
            int y0 = (int)y0f, x0 = (int)x0f, y1 = y0 + 1, x1 = x0 + 1;
            bool vy0 = ((unsigned)y0 < HH), vy1 = ((unsigned)y1 < HH);
            bool vx0 = ((unsigned)x0 < WW), vx1 = ((unsigned)x1 < WW);
            wA00 = (1.f - dy) * (1.f - dx) * ((vy0 && vx0) ? 1.f : 0.f);
            wA01 = (1.f - dy) * dx         * ((vy0 && vx1) ? 1.f : 0.f);
            wA10 = dy * (1.f - dx)         * ((vy1 && vx0) ? 1.f : 0.f);
            wA11 = dy * dx                 * ((vy1 && vx1) ? 1.f : 0.f);
            int y0c = min(max(y0, 0), HH - 1), y1c = min(max(y1, 0), HH - 1);
            int x0c = min(max(x0, 0), WW - 1), x1c = min(max(x1, 0), WW - 1);
            iA00 = y0c * WW + x0c; iA01 = y0c * WW + x1c;
            iA10 = y1c * WW + x0c; iA11 = y1c * WW + x1c;
        }
        float wB00, wB01, wB10, wB11; int iB00, iB01, iB10, iB11;
        {
            float sy = (float)(h0 + i) + offB[2 * k];
            float sx = (float)(w - 1 + j) + offB[2 * k + 1];
            float y0f = floorf(sy), x0f = floorf(sx);
            float dy = sy - y0f, dx = sx - x0f;
            int y0 = (int)y0f, x0 = (int)x0f, y1 = y0 + 1, x1 = x0 + 1;
            bool vy0 = ((unsigned)y0 < HH), vy1 = ((unsigned)y1 < HH);
            bool vx0 = ((unsigned)x0 < WW), vx1 = ((unsigned)x1 < WW);
            wB00 = (1.f - dy) * (1.f - dx) * ((vy0 && vx0) ? 1.f : 0.f);
            wB01 = (1.f - dy) * dx         * ((vy0 && vx1) ? 1.f : 0.f);
            wB10 = dy * (1.f - dx)         * ((vy1 && vx0) ? 1.f : 0.f);
            wB11 = dy * dx                 * ((vy1 && vx1) ? 1.f : 0.f);
            int y0c = min(max(y0, 0), HH - 1), y1c = min(max(y1, 0), HH - 1);
            int x0c = min(max(x0, 0), WW - 1), x1c = min(max(x1, 0), WW - 1);
            iB00 = y0c * WW + x0c; iB01 = y0c * WW + x1c;
            iB10 = y1c * WW + x0c; iB11 = y1c * WW + x1c;
        }

        const float* wkb = &sw[k * CC * CC + oBase];

        #pragma unroll 1
        for (int c4 = 0; c4 < NP; c4++) {
            const float4* pc = g_feat + (c4 * BB + b) * HH * WW;
            float sA0, sA1, sA2, sA3;
            {
                float4 a00 = pc[iA00], a01 = pc[iA01], a10 = pc[iA10], a11 = pc[iA11];
                sA0 = wA00 * a00.x + wA01 * a01.x + wA10 * a10.x + wA11 * a11.x;
                sA1 = wA00 * a00.y + wA01 * a01.y + wA10 * a10.y + wA11 * a11.y;
                sA2 = wA00 * a00.z + wA01 * a01.z + wA10 * a10.z + wA11 * a11.z;
                sA3 = wA00 * a00.w + wA01 * a01.w + wA10 * a10.w + wA11 * a11.w;
            }
            float sB0, sB1, sB2, sB3;
            {
                float4 b00 = pc[iB00], b01 = pc[iB01], b10 = pc[iB10], b11 = pc[iB11];
                sB0 = wB00 * b00.x + wB01 * b01.x + wB10 * b10.x + wB11 * b11.x;
                sB1 = wB00 * b00.y + wB01 * b01.y + wB10 * b10.y + wB11 * b11.y;
                sB2 = wB00 * b00.z + wB01 * b01.z + wB10 * b10.z + wB11 * b11.z;
                sB3 = wB00 * b00.w + wB01 * b01.w + wB10 * b10.w + wB11 * b11.w;
            }
            const float sAv[4] = {sA0, sA1, sA2, sA3};
            const float sBv[4] = {sB0, sB1, sB2, sB3};
            #pragma unroll
            for (int cc = 0; cc < 4; cc++) {
                ull sa = pack2(sAv[cc], sAv[cc]);
                ull sb2 = pack2(sBv[cc], sBv[cc]);
                const ulonglong2* wp = (const ulonglong2*)(wkb + (c4 * 4 + cc) * CC);
                #pragma unroll
                for (int q = 0; q < 8; q++) {
                    ulonglong2 ww = wp[q];
                    FMA2(accA[2 * q], sa, ww.x);
                    FMA2(accA[2 * q + 1], sa, ww.y);
                    FMA2(accB[2 * q], sb2, ww.x);
                    FMA2(accB[2 * q + 1], sb2, ww.y);
                }
            }
        }
    }

    #pragma unroll
    for (int q = 0; q < 16; q++) {
        int o = oBase + 2 * q;
        float2 va = unpack2(accA[q]);
        float2 vb = unpack2(accB[q]);
        float b0 = db[o], b1 = db[o + 1];
        out[((b * CC + o) * HH + h0) * WW + w]         = va.x + b0;
        out[((b * CC + o + 1) * HH + h0) * WW + w]     = va.y + b1;
        out[((b * CC + o) * HH + h0 + 1) * WW + w]     = vb.x + b0;
        out[((b * CC + o + 1) * HH + h0 + 1) * WW + w] = vb.y + b1;
    }
}

// ---------------------------------------------------------------------------
extern "C" void kernel_launch(void* const* d_in, const int* in_sizes, int n_in,
                              void* d_out, int out_size) {
    const float* x        = (const float*)d_in[0];
    const float* conv_w   = (const float*)d_in[1];
    const float* conv_b   = (const float*)d_in[2];
    const float* offset_w = (const float*)d_in[3];
    const float* offset_b = (const float*)d_in[4];
    const float* deform_w = (const float*)d_in[5];
    const float* deform_b = (const float*)d_in[6];
    float* out = (float*)d_out;

    cudaFuncSetAttribute(deform_kernel, cudaFuncAttributeMaxDynamicSharedMemorySize,
                         9 * CC * CC * (int)sizeof(float));

    prep_kernel<<<96, 512>>>(conv_w, offset_w, deform_w);
    conv_in_kernel<<<BB * HH, 256>>>(x, conv_b);
    conv_off_kernel<<<BB * HH / 2, 256>>>(offset_b);
    deform_kernel<<<BB * HH / 2, 512, 9 * CC * CC * (int)sizeof(float)>>>(deform_b, out);
}

// round 3
// speedup vs baseline: 2.2635x; 1.4284x over previous
#include <cuda_runtime.h>

#define BB   4
#define HH   256
#define WW   256
#define CC   64
#define CIN  3
#define OFFC 18
#define OFFP 20
#define NP   16

// Scratch (allocation-free)
__device__ float4 g_feat[NP * BB * HH * WW];       // NC4HW4 features
__device__ float  g_off [BB * HH * WW * OFFC];     // NHWC offsets
__device__ float  g_cwT [CIN * 9 * CC];
__device__ float  g_owT [CC * 9 * OFFP];
__device__ float  g_dwT [9 * CC * CC];             // [k][c][o]

typedef unsigned long long ull;

__device__ __forceinline__ ull pack2(float lo, float hi) {
    ull r; asm("mov.b64 %0, {%1,%2};" : "=l"(r) : "f"(lo), "f"(hi)); return r;
}
__device__ __forceinline__ float2 unpack2(ull v) {
    float2 r; asm("mov.b64 {%0,%1}, %2;" : "=f"(r.x), "=f"(r.y) : "l"(v)); return r;
}
#define FMA2(a, x, y) asm("fma.rn.f32x2 %0, %1, %2, %0;" : "+l"(a) : "l"(x), "l"(y))

// ---------------------------------------------------------------------------
__global__ void prep_kernel(const float* __restrict__ cw,
                            const float* __restrict__ ow,
                            const float* __restrict__ dw) {
    int t = blockIdx.x * blockDim.x + threadIdx.x;
    int nt = gridDim.x * blockDim.x;
    for (int idx = t; idx < CIN * 9 * CC; idx += nt) {
        int o = idx % CC, r = idx / CC;
        g_cwT[idx] = cw[o * (CIN * 9) + r];
    }
    for (int idx = t; idx < CC * 9 * OFFP; idx += nt) {
        int oc = idx % OFFP, ct = idx / OFFP;
        g_owT[idx] = (oc < OFFC) ? ow[oc * (CC * 9) + ct] : 0.0f;
    }
    for (int idx = t; idx < 9 * CC * CC; idx += nt) {
        int o = idx % CC, c = (idx / CC) % CC, k = idx / (CC * CC);
        g_dwT[idx] = dw[(o * CC + c) * 9 + k];
    }
}

// ---------------------------------------------------------------------------
// Kernel 1: x NCHW -> feat NC4HW4, 3x3 conv pad 1
// ---------------------------------------------------------------------------
__global__ void __launch_bounds__(256) conv_in_kernel(const float* __restrict__ x,
                                                      const float* __restrict__ cb) {
    __shared__ __align__(16) float sw[CIN * 9 * CC];
    __shared__ float sb[CC];
    for (int idx = threadIdx.x; idx < CIN * 9 * CC; idx += 256) sw[idx] = g_cwT[idx];
    if (threadIdx.x < CC) sb[threadIdx.x] = cb[threadIdx.x];
    __syncthreads();

    const int b = blockIdx.x / HH, h = blockIdx.x % HH, w = threadIdx.x;

    ull acc[32];
    #pragma unroll
    for (int q = 0; q < 32; q++) acc[q] = pack2(sb[2 * q], sb[2 * q + 1]);

    #pragma unroll 1
    for (int ci = 0; ci < CIN; ci++) {
        #pragma unroll
        for (int i = 0; i < 3; i++) {
            int y = h - 1 + i;
            bool yv = ((unsigned)y < HH);
            #pragma unroll
            for (int j = 0; j < 3; j++) {
                int xx = w - 1 + j;
                float v = (yv && (unsigned)xx < WW) ? x[((b * CIN + ci) * HH + y) * WW + xx] : 0.0f;
                ull s2 = pack2(v, v);
                const ulonglong2* wp = (const ulonglong2*)&sw[(ci * 9 + i * 3 + j) * CC];
                #pragma unroll
                for (int q = 0; q < 16; q++) {
                    ulonglong2 ww = wp[q];
                    FMA2(acc[2 * q], s2, ww.x);
                    FMA2(acc[2 * q + 1], s2, ww.y);
                }
            }
        }
    }

    const int ppix = h * WW + w;
    #pragma unroll
    for (int q4 = 0; q4 < NP; q4++) {
        float2 lo = unpack2(acc[2 * q4]);
        float2 hi = unpack2(acc[2 * q4 + 1]);
        g_feat[(q4 * BB + b) * HH * WW + ppix] = make_float4(lo.x, lo.y, hi.x, hi.y);
    }
}

// ---------------------------------------------------------------------------
// Kernel 2: feat NC4HW4 -> offsets NHWC(18), 2 rows per block
// ---------------------------------------------------------------------------
__global__ void __launch_bounds__(256) conv_off_kernel(const float* __restrict__ ob) {
    __shared__ __align__(16) float sw[CC * 9 * OFFP];
    for (int idx = threadIdx.x; idx < CC * 9 * OFFP; idx += 256) sw[idx] = g_owT[idx];
    __syncthreads();

    const int b = blockIdx.x / (HH / 2);
    const int h0 = (blockIdx.x % (HH / 2)) * 2;
    const int w = threadIdx.x;

    ull accA[9], accB[9];
    #pragma unroll
    for (int q = 0; q < 9; q++) {
        ull t = pack2(ob[2 * q], ob[2 * q + 1]);
        accA[q] = t; accB[q] = t;
    }

    #pragma unroll 1
    for (int i = 0; i < 3; i++) {
        int yA = h0 - 1 + i, yB = h0 + i;
        bool yAv = ((unsigned)yA < HH), yBv = ((unsigned)yB < HH);
        #pragma unroll 1
        for (int j = 0; j < 3; j++) {
            int xx = w - 1 + j;
            bool xv = ((unsigned)xx < WW);
            bool vA = yAv && xv, vB = yBv && xv;
            int xc = xv ? xx : 0;
            int iA = (vA ? yA : 0) * WW + xc;
            int iB = (vB ? yB : 0) * WW + xc;
            const int tap = i * 3 + j;
            #pragma unroll 1
            for (int c4 = 0; c4 < NP; c4++) {
                const float4* pc = g_feat + (c4 * BB + b) * HH * WW;
                float4 fa = vA ? pc[iA] : make_float4(0.f, 0.f, 0.f, 0.f);
                float4 fb = vB ? pc[iB] : make_float4(0.f, 0.f, 0.f, 0.f);
                const float fav[4] = {fa.x, fa.y, fa.z, fa.w};
                const float fbv[4] = {fb.x, fb.y, fb.z, fb.w};
                #pragma unroll
                for (int cc = 0; cc < 4; cc++) {
                    ull sa = pack2(fav[cc], fav[cc]);
                    ull sb2 = pack2(fbv[cc], fbv[cc]);
                    const float* wrow = &sw[((c4 * 4 + cc) * 9 + tap) * OFFP];
                    const ulonglong2* wp = (const ulonglong2*)wrow;
                    #pragma unroll
                    for (int q2 = 0; q2 < 4; q2++) {
                        ulonglong2 ww = wp[q2];
                        FMA2(accA[2 * q2], sa, ww.x);
                        FMA2(accA[2 * q2 + 1], sa, ww.y);
                        FMA2(accB[2 * q2], sb2, ww.x);
                        FMA2(accB[2 * q2 + 1], sb2, ww.y);
                    }
                    ull w8 = *(const ull*)(wrow + 16);
                    FMA2(accA[8], sa, w8);
                    FMA2(accB[8], sb2, w8);
                }
            }
        }
    }

    float* opA = &g_off[((b * HH + h0) * WW + w) * OFFC];
    float* opB = opA + WW * OFFC;
    #pragma unroll
    for (int q = 0; q < 9; q++) {
        ((float2*)opA)[q] = unpack2(accA[q]);
        ((float2*)opB)[q] = unpack2(accB[q]);
    }
}

// ---------------------------------------------------------------------------
// Kernel 3: deform conv as staged GEMM.
// Block = 256 threads, 128 pixels (half a row). Per tap: gather+bilinear into
// S[64][128] smem (double buffered), stream W tap tile (16KB, double buffered),
// register-tiled GEMM 4px x 8o per thread. 96KB smem -> 2 CTAs/SM.
// ---------------------------------------------------------------------------
__device__ __forceinline__ void tap_coords(int h, int w_img, int kk,
                                           const float* off,
                                           float& w00, float& w01, float& w10, float& w11,
                                           int& i00, int& i01, int& i10, int& i11) {
    const int i = kk / 3, j = kk - 3 * i;
    float sy = (float)(h - 1 + i) + off[2 * kk];
    float sx = (float)(w_img - 1 + j) + off[2 * kk + 1];
    float y0f = floorf(sy), x0f = floorf(sx);
    float dy = sy - y0f, dx = sx - x0f;
    int y0 = (int)y0f, x0 = (int)x0f, y1 = y0 + 1, x1 = x0 + 1;
    bool vy0 = ((unsigned)y0 < HH), vy1 = ((unsigned)y1 < HH);
    bool vx0 = ((unsigned)x0 < WW), vx1 = ((unsigned)x1 < WW);
    w00 = (1.f - dy) * (1.f - dx) * ((vy0 && vx0) ? 1.f : 0.f);
    w01 = (1.f - dy) * dx         * ((vy0 && vx1) ? 1.f : 0.f);
    w10 = dy * (1.f - dx)         * ((vy1 && vx0) ? 1.f : 0.f);
    w11 = dy * dx                 * ((vy1 && vx1) ? 1.f : 0.f);
    int y0c = min(max(y0, 0), HH - 1), y1c = min(max(y1, 0), HH - 1);
    int x0c = min(max(x0, 0), WW - 1), x1c = min(max(x1, 0), WW - 1);
    i00 = y0c * WW + x0c; i01 = y0c * WW + x1c;
    i10 = y1c * WW + x0c; i11 = y1c * WW + x1c;
}

__global__ void __launch_bounds__(256, 2) deform_kernel(const float* __restrict__ db,
                                                        float* __restrict__ out) {
    extern __shared__ __align__(16) float smem[];
    float* Sb0 = smem;            // 8192 floats (S[64][128])
    float* Sb1 = smem + 8192;
    float* Wb0 = smem + 16384;    // 4096 floats (W[64][64])
    float* Wb1 = smem + 20480;

    const int tid = threadIdx.x;
    const int bi = blockIdx.x;
    const int b = bi >> 9;
    const int rest = bi & 511;
    const int h = rest >> 1;
    const int wbase = (rest & 1) << 7;

    // gather mapping: thread -> pixel (px_g), plane half
    const int px_g = tid & 127;
    const int pg_half = tid >> 7;
    const int w_img = wbase + px_g;

    // GEMM mapping: warp -> 8 outputs, lane -> 4 pixels
    const int lane = tid & 31;
    const int o_t = tid >> 5;

    // preload all 18 offsets for this thread's gather pixel
    float off[18];
    {
        const float2* op2 = (const float2*)(g_off + (((b * HH + h) * WW) + w_img) * OFFC);
        #pragma unroll
        for (int q = 0; q < 9; q++) { float2 t2 = op2[q]; off[2 * q] = t2.x; off[2 * q + 1] = t2.y; }
    }

    const float4* gW = (const float4*)g_dwT;

    // Prologue: load W(0) and gather tap 0 into buffer 0
    #pragma unroll
    for (int q = 0; q < 4; q++)
        ((float4*)Wb0)[q * 256 + tid] = gW[q * 256 + tid];
    {
        float w00, w01, w10, w11; int i00, i01, i10, i11;
        tap_coords(h, w_img, 0, off, w00, w01, w10, w11, i00, i01, i10, i11);
        #pragma unroll
        for (int p = 0; p < 8; p++) {
            const int pl = pg_half * 8 + p;
            const float4* pc = g_feat + (pl * BB + b) * HH * WW;
            float4 c00 = pc[i00], c01 = pc[i01], c10 = pc[i10], c11 = pc[i11];
            float s0 = w00 * c00.x + w01 * c01.x + w10 * c10.x + w11 * c11.x;
            float s1 = w00 * c00.y + w01 * c01.y + w10 * c10.y + w11 * c11.y;
            float s2 = w00 * c00.z + w01 * c01.z + w10 * c10.z + w11 * c11.z;
            float s3 = w00 * c00.w + w01 * c01.w + w10 * c10.w + w11 * c11.w;
            const int cb = pl * 4;
            Sb0[(cb + 0) * 128 + px_g] = s0;
            Sb0[(cb + 1) * 128 + px_g] = s1;
            Sb0[(cb + 2) * 128 + px_g] = s2;
            Sb0[(cb + 3) * 128 + px_g] = s3;
        }
    }
    __syncthreads();

    ull acc[4][4];
    #pragma unroll
    for (int pp = 0; pp < 4; pp++)
        #pragma unroll
        for (int op = 0; op < 4; op++) acc[pp][op] = 0ull;

    #pragma unroll 1
    for (int k = 0; k < 9; k++) {
        const float* Sb = (k & 1) ? Sb1 : Sb0;
        const float* Wb = (k & 1) ? Wb1 : Wb0;
        float* Sd = (k & 1) ? Sb0 : Sb1;
        float4* Wd = (float4*)((k & 1) ? Wb0 : Wb1);
        const int kk = k + 1;
        const bool dog = (kk < 9);

        float w00 = 0.f, w01 = 0.f, w10 = 0.f, w11 = 0.f;
        int i00 = 0, i01 = 0, i10 = 0, i11 = 0;
        if (dog) tap_coords(h, w_img, kk, off, w00, w01, w10, w11, i00, i01, i10, i11);
        const float4* gWk = gW + kk * 1024;

        #pragma unroll
        for (int p = 0; p < 8; p++) {
            float4 c00, c01, c10, c11, wt;
            if (dog) {
                const int pl = pg_half * 8 + p;
                const float4* pc = g_feat + (pl * BB + b) * HH * WW;
                c00 = pc[i00]; c01 = pc[i01]; c10 = pc[i10]; c11 = pc[i11];
                if (p < 4) wt = gWk[p * 256 + tid];
            }

            // GEMM chunk: c = p*8 .. p*8+7
            #pragma unroll
            for (int cc = 0; cc < 8; cc++) {
                const int c = p * 8 + cc;
                float4 sv = *(const float4*)(Sb + c * 128 + lane * 4);
                const ulonglong2* wrow = (const ulonglong2*)(Wb + c * 64 + o_t * 8);
                ulonglong2 wA = wrow[0];
                ulonglong2 wB = wrow[1];
                ull s;
                s = pack2(sv.x, sv.x);
                FMA2(acc[0][0], s, wA.x); FMA2(acc[0][1], s, wA.y);
                FMA2(acc[0][2], s, wB.x); FMA2(acc[0][3], s, wB.y);
                s = pack2(sv.y, sv.y);
                FMA2(acc[1][0], s, wA.x); FMA2(acc[1][1], s, wA.y);
                FMA2(acc[1][2], s, wB.x); FMA2(acc[1][3], s, wB.y);
                s = pack2(sv.z, sv.z);
                FMA2(acc[2][0], s, wA.x); FMA2(acc[2][1], s, wA.y);
                FMA2(acc[2][2], s, wB.x); FMA2(acc[2][3], s, wB.y);
                s = pack2(sv.w, sv.w);
                FMA2(acc[3][0], s, wA.x); FMA2(acc[3][1], s, wA.y);
                FMA2(acc[3][2], s, wB.x); FMA2(acc[3][3], s, wB.y);
            }

            if (dog) {
                float s0 = w00 * c00.x + w01 * c01.x + w10 * c10.x + w11 * c11.x;
                float s1 = w00 * c00.y + w01 * c01.y + w10 * c10.y + w11 * c11.y;
                float s2 = w00 * c00.z + w01 * c01.z + w10 * c10.z + w11 * c11.z;
                float s3 = w00 * c00.w + w01 * c01.w + w10 * c10.w + w11 * c11.w;
                const int cb = (pg_half * 8 + p) * 4;
                Sd[(cb + 0) * 128 + px_g] = s0;
                Sd[(cb + 1) * 128 + px_g] = s1;
                Sd[(cb + 2) * 128 + px_g] = s2;
                Sd[(cb + 3) * 128 + px_g] = s3;
                if (p < 4) Wd[p * 256 + tid] = wt;
            }
        }
        __syncthreads();
    }

    // Epilogue: add bias, write NCHW
    const float2* db2 = (const float2*)db;
    #pragma unroll
    for (int op = 0; op < 4; op++) {
        float2 bz = db2[o_t * 4 + op];
        const int o = o_t * 8 + op * 2;
        #pragma unroll
        for (int pp = 0; pp < 4; pp++) {
            float2 v = unpack2(acc[pp][op]);
            const int base = ((b * CC + o) * HH + h) * WW + wbase + lane * 4 + pp;
            out[base] = v.x + bz.x;
            out[base + HH * WW] = v.y + bz.y;
        }
    }
}

// ---------------------------------------------------------------------------
extern "C" void kernel_launch(void* const* d_in, const int* in_sizes, int n_in,
                              void* d_out, int out_size) {
    const float* x        = (const float*)d_in[0];
    const float* conv_w   = (const float*)d_in[1];
    const float* conv_b   = (const float*)d_in[2];
    const float* offset_w = (const float*)d_in[3];
    const float* offset_b = (const float*)d_in[4];
    const float* deform_w = (const float*)d_in[5];
    const float* deform_b = (const float*)d_in[6];
    float* out = (float*)d_out;

    const int dsm = 24576 * (int)sizeof(float);   // 96KB
    cudaFuncSetAttribute(deform_kernel, cudaFuncAttributeMaxDynamicSharedMemorySize, dsm);

    prep_kernel<<<96, 512>>>(conv_w, offset_w, deform_w);
    conv_in_kernel<<<BB * HH, 256>>>(x, conv_b);
    conv_off_kernel<<<BB * HH / 2, 256>>>(offset_b);
    deform_kernel<<<BB * HH * 2, 256, dsm>>>(deform_b, out);
}